// round 4
// baseline (speedup 1.0000x reference)
#include <cuda_runtime.h>
#include <cuda_bf16.h>

// out[b,s,h,d] = cos(x[b,s,h,d]) * cos(params[h,d,0])
// x: [8, 8192, 1024] fp32 = 16,777,216 float4; params: [16, 64, 3] fp32.
//
// channel4 = float4_index % 256 == threadIdx.x (all strides are multiples
// of 256) -> ry in 4 registers per thread, computed once from params.
//
// Persistent single-wave stream: 888 CTAs (148 SMs x 6 resident @ 40 regs),
// each grid-striding over 2048-float4 chunks. UNROLL=8 loads front-batched.

#define THREADS 256
#define UNROLL  8
#define GRID    888   // 148 SMs * 6 CTAs (256 thr, ~40 regs) = one full wave

__global__ __launch_bounds__(THREADS)
void qa_cos_kernel(const float4* __restrict__ x,
                   const float* __restrict__ params,
                   float4* __restrict__ out,
                   int n4)
{
    const int tid = threadIdx.x;

    // Per-thread constant ry (channel group == tid).
    const int c = tid * 4;
    float4 r;
    r.x = cosf(params[(c + 0) * 3]);
    r.y = cosf(params[(c + 1) * 3]);
    r.z = cosf(params[(c + 2) * 3]);
    r.w = cosf(params[(c + 3) * 3]);

    const int chunk_elems = THREADS * UNROLL;       // 2048 float4 per chunk
    const int stride      = GRID * chunk_elems;

    for (int base = blockIdx.x * chunk_elems + tid; base < n4; base += stride) {
        if (base + (UNROLL - 1) * THREADS < n4) {
            float4 v[UNROLL];
#pragma unroll
            for (int i = 0; i < UNROLL; i++)
                v[i] = x[base + i * THREADS];
#pragma unroll
            for (int i = 0; i < UNROLL; i++) {
                float4 o;
                o.x = __cosf(v[i].x) * r.x;
                o.y = __cosf(v[i].y) * r.y;
                o.z = __cosf(v[i].z) * r.z;
                o.w = __cosf(v[i].w) * r.w;
                out[base + i * THREADS] = o;
            }
        } else {
#pragma unroll
            for (int i = 0; i < UNROLL; i++) {
                int idx = base + i * THREADS;
                if (idx < n4) {
                    float4 v = x[idx];
                    float4 o;
                    o.x = __cosf(v.x) * r.x;
                    o.y = __cosf(v.y) * r.y;
                    o.z = __cosf(v.z) * r.z;
                    o.w = __cosf(v.w) * r.w;
                    out[idx] = o;
                }
            }
        }
    }
}

extern "C" void kernel_launch(void* const* d_in, const int* in_sizes, int n_in,
                              void* d_out, int out_size)
{
    const float* x      = (const float*)d_in[0];
    const float* params = (const float*)d_in[1];
    float* out          = (float*)d_out;

    int n  = in_sizes[0];          // 67,108,864
    int n4 = n >> 2;               // 16,777,216 float4s

    qa_cos_kernel<<<GRID, THREADS>>>((const float4*)x, params, (float4*)out, n4);
}

// round 5
// speedup vs baseline: 1.1201x; 1.1201x over previous
#include <cuda_runtime.h>
#include <cuda_bf16.h>

// out[b,s,h,d] = cos(x[b,s,h,d]) * cos(params[h,d,0])
// x: [8, 8192, 1024] fp32 = 16,777,216 float4; params: [16, 64, 3] fp32.
//
// channel4 = float4_index % 128: with 128 threads/block, thread t's channel
// group is (t) mod... NOTE: 1024 channels = 256 float4 groups. With
// THREADS=128, a thread touches groups {tid, tid+128} alternating by i
// parity (stride 128 within the chunk). So each thread needs TWO ry float4s:
// ry[tid] and ry[tid+128], selected by iteration parity.
//
// Many small CTAs (16384) for CTA-level load/store pipelining; 8 float4
// per thread, loads front-batched; streaming cache hints.

#define THREADS 128
#define UNROLL  8

__global__ __launch_bounds__(THREADS)
void qa_cos_kernel(const float4* __restrict__ x,
                   const float* __restrict__ params,
                   float4* __restrict__ out,
                   int n4)
{
    const int tid = threadIdx.x;

    // Thread touches float4-groups (base + i*128) mod 256 = tid (i even),
    // tid+128 (i odd), since base = blk*1024 + tid and 1024 % 256 == 0.
    const int c0 = tid * 4;
    const int c1 = (tid + 128) * 4;
    float4 r0, r1;
    r0.x = cosf(params[(c0 + 0) * 3]);
    r0.y = cosf(params[(c0 + 1) * 3]);
    r0.z = cosf(params[(c0 + 2) * 3]);
    r0.w = cosf(params[(c0 + 3) * 3]);
    r1.x = cosf(params[(c1 + 0) * 3]);
    r1.y = cosf(params[(c1 + 1) * 3]);
    r1.z = cosf(params[(c1 + 2) * 3]);
    r1.w = cosf(params[(c1 + 3) * 3]);

    const int base = blockIdx.x * (THREADS * UNROLL) + tid;

    if (base + (UNROLL - 1) * THREADS < n4) {
        float4 v[UNROLL];
#pragma unroll
        for (int i = 0; i < UNROLL; i++)
            v[i] = __ldcs(&x[base + i * THREADS]);
#pragma unroll
        for (int i = 0; i < UNROLL; i++) {
            const float4 r = (i & 1) ? r1 : r0;
            float4 o;
            o.x = __cosf(v[i].x) * r.x;
            o.y = __cosf(v[i].y) * r.y;
            o.z = __cosf(v[i].z) * r.z;
            o.w = __cosf(v[i].w) * r.w;
            __stcs(&out[base + i * THREADS], o);
        }
    } else {
#pragma unroll
        for (int i = 0; i < UNROLL; i++) {
            int idx = base + i * THREADS;
            if (idx < n4) {
                const float4 r = (i & 1) ? r1 : r0;
                float4 v = __ldcs(&x[idx]);
                float4 o;
                o.x = __cosf(v.x) * r.x;
                o.y = __cosf(v.y) * r.y;
                o.z = __cosf(v.z) * r.z;
                o.w = __cosf(v.w) * r.w;
                __stcs(&out[idx], o);
            }
        }
    }
}

extern "C" void kernel_launch(void* const* d_in, const int* in_sizes, int n_in,
                              void* d_out, int out_size)
{
    const float* x      = (const float*)d_in[0];
    const float* params = (const float*)d_in[1];
    float* out          = (float*)d_out;

    int n  = in_sizes[0];          // 67,108,864
    int n4 = n >> 2;               // 16,777,216 float4s
    int per_block = THREADS * UNROLL;               // 1024
    int grid = (n4 + per_block - 1) / per_block;    // 16384 blocks

    qa_cos_kernel<<<grid, THREADS>>>((const float4*)x, params, (float4*)out, n4);
}

// round 6
// speedup vs baseline: 1.1300x; 1.0089x over previous
#include <cuda_runtime.h>
#include <cuda_bf16.h>
#include <cstdint>

// out[i] = cos(x[i]) * cos(params[(i % 1024) * 3])
// x: 8*8192*1024 fp32 = 256MB; params: [16,64,3].
//
// Bulk-burst streaming: each CTA moves one 16KB tile via cp.async.bulk
// (global->smem), computes in smem, and writes back via cp.async.bulk
// (smem->global). 16KB contiguous bursts minimize HBM read/write
// turnaround vs 512B warp transactions.
//
// Tile = 4096 floats = 1024 float4 = 4 channel-blocks of 1024, so the
// float4 channel-group of element (tid + i*256) within any tile is just
// tid -> ry lives in 4 registers per thread.

#define THREADS 256
#define TILE_BYTES 16384
#define TILE_F4    (TILE_BYTES / 16)   // 1024
#define PER_THREAD (TILE_F4 / THREADS) // 4

__global__ __launch_bounds__(THREADS)
void qa_bulk_kernel(const float* __restrict__ x,
                    const float* __restrict__ params,
                    float* __restrict__ out)
{
    __shared__ __align__(128) float4 s_in[TILE_F4];
    __shared__ __align__(128) float4 s_out[TILE_F4];
    __shared__ __align__(8) uint64_t mbar;

    const int tid = threadIdx.x;

    // Per-thread ry (channel group == tid within every tile).
    const int c = tid * 4;
    float4 r;
    r.x = cosf(params[(c + 0) * 3]);
    r.y = cosf(params[(c + 1) * 3]);
    r.z = cosf(params[(c + 2) * 3]);
    r.w = cosf(params[(c + 3) * 3]);

    uint32_t mbar_addr;
    {
        uint64_t t;
        asm("cvta.to.shared.u64 %0, %1;" : "=l"(t) : "l"(&mbar));
        mbar_addr = (uint32_t)t;
    }
    uint32_t s_in_addr, s_out_addr;
    {
        uint64_t t;
        asm("cvta.to.shared.u64 %0, %1;" : "=l"(t) : "l"(s_in));
        s_in_addr = (uint32_t)t;
        asm("cvta.to.shared.u64 %0, %1;" : "=l"(t) : "l"(s_out));
        s_out_addr = (uint32_t)t;
    }

    const float* gsrc = x + (size_t)blockIdx.x * (TILE_BYTES / 4);
    float*       gdst = out + (size_t)blockIdx.x * (TILE_BYTES / 4);

    if (tid == 0) {
        asm volatile("mbarrier.init.shared.b64 [%0], %1;"
                     :: "r"(mbar_addr), "r"(1) : "memory");
    }
    __syncthreads();

    if (tid == 0) {
        asm volatile("mbarrier.arrive.expect_tx.shared.b64 _, [%0], %1;"
                     :: "r"(mbar_addr), "r"((uint32_t)TILE_BYTES) : "memory");
        asm volatile(
            "cp.async.bulk.shared::cta.global.mbarrier::complete_tx::bytes "
            "[%0], [%1], %2, [%3];"
            :: "r"(s_in_addr), "l"(gsrc), "r"((uint32_t)TILE_BYTES), "r"(mbar_addr)
            : "memory");
    }

    // Wait for tile arrival (parity 0).
    {
        uint32_t done;
        asm volatile(
            "{\n\t.reg .pred p;\n\t"
            "mbarrier.try_wait.parity.acquire.cta.shared::cta.b64 p, [%1], 0;\n\t"
            "selp.b32 %0, 1, 0, p;\n\t}"
            : "=r"(done) : "r"(mbar_addr) : "memory");
        if (!done) {
            asm volatile(
                "{\n\t.reg .pred P1;\n\t"
                "WL_%=:\n\t"
                "mbarrier.try_wait.parity.acquire.cta.shared::cta.b64 P1, [%0], 0, 0x989680;\n\t"
                "@P1 bra.uni WD_%=;\n\t"
                "bra.uni WL_%=;\n\t"
                "WD_%=:\n\t}"
                :: "r"(mbar_addr) : "memory");
        }
    }

#pragma unroll
    for (int i = 0; i < PER_THREAD; i++) {
        float4 v = s_in[tid + i * THREADS];
        float4 o;
        o.x = __cosf(v.x) * r.x;
        o.y = __cosf(v.y) * r.y;
        o.z = __cosf(v.z) * r.z;
        o.w = __cosf(v.w) * r.w;
        s_out[tid + i * THREADS] = o;
    }
    __syncthreads();

    if (tid == 0) {
        asm volatile("fence.proxy.async.shared::cta;" ::: "memory");
        asm volatile(
            "cp.async.bulk.global.shared::cta.bulk_group [%0], [%1], %2;"
            :: "l"(gdst), "r"(s_out_addr), "r"((uint32_t)TILE_BYTES)
            : "memory");
        asm volatile("cp.async.bulk.commit_group;" ::: "memory");
        asm volatile("cp.async.bulk.wait_group.read 0;" ::: "memory");
    }
}

// Fallback for any tail elements (not expected for this shape).
__global__ void qa_tail_kernel(const float* __restrict__ x,
                               const float* __restrict__ params,
                               float* __restrict__ out,
                               int start, int n)
{
    int i = start + blockIdx.x * blockDim.x + threadIdx.x;
    if (i < n) {
        float ry = cosf(params[(i & 1023) * 3]);
        out[i] = __cosf(x[i]) * ry;
    }
}

extern "C" void kernel_launch(void* const* d_in, const int* in_sizes, int n_in,
                              void* d_out, int out_size)
{
    const float* x      = (const float*)d_in[0];
    const float* params = (const float*)d_in[1];
    float* out          = (float*)d_out;

    int n = in_sizes[0];                     // 67,108,864
    int floats_per_tile = TILE_BYTES / 4;    // 4096
    int ntiles = n / floats_per_tile;        // 16384
    int covered = ntiles * floats_per_tile;

    if (ntiles > 0)
        qa_bulk_kernel<<<ntiles, THREADS>>>(x, params, out);

    int tail = n - covered;
    if (tail > 0) {
        int tb = 256;
        qa_tail_kernel<<<(tail + tb - 1) / tb, tb>>>(x, params, out, covered, n);
    }
}

// round 7
// speedup vs baseline: 1.1331x; 1.0027x over previous
#include <cuda_runtime.h>
#include <cuda_bf16.h>
#include <cstdint>

// out[i] = cos(x[i]) * cos(params[(i % 1024) * 3])
// x: 8*8192*1024 fp32 = 256MB; params: [16,64,3].
//
// Double-buffered TMA bulk stream: each CTA owns TWO consecutive 16KB
// tiles. Both bulk loads are issued immediately (2x in-flight reads per
// CTA from cycle 0); compute is done in-place in smem; each tile is
// bulk-stored as soon as it's ready. 16KB contiguous bursts; grid=8192.
//
// Tile = 4096 floats = 4 channel-blocks of 1024 -> float4 channel group
// of (tid + i*256) within any tile == tid -> ry in 4 registers.

#define THREADS 256
#define TILE_BYTES 16384
#define TILE_F4    (TILE_BYTES / 16)   // 1024
#define PER_THREAD (TILE_F4 / THREADS) // 4

__device__ __forceinline__ uint32_t smem_u32(const void* p) {
    uint64_t t;
    asm("cvta.to.shared.u64 %0, %1;" : "=l"(t) : "l"(p));
    return (uint32_t)t;
}

__device__ __forceinline__ void mbar_wait0(uint32_t mbar) {
    uint32_t done;
    asm volatile(
        "{\n\t.reg .pred p;\n\t"
        "mbarrier.try_wait.parity.acquire.cta.shared::cta.b64 p, [%1], 0;\n\t"
        "selp.b32 %0, 1, 0, p;\n\t}"
        : "=r"(done) : "r"(mbar) : "memory");
    if (!done) {
        asm volatile(
            "{\n\t.reg .pred P1;\n\t"
            "WL_%=:\n\t"
            "mbarrier.try_wait.parity.acquire.cta.shared::cta.b64 P1, [%0], 0, 0x989680;\n\t"
            "@P1 bra.uni WD_%=;\n\t"
            "bra.uni WL_%=;\n\t"
            "WD_%=:\n\t}"
            :: "r"(mbar) : "memory");
    }
}

__global__ __launch_bounds__(THREADS)
void qa_bulk2_kernel(const float* __restrict__ x,
                     const float* __restrict__ params,
                     float* __restrict__ out)
{
    __shared__ __align__(128) float4 s_buf[2][TILE_F4];
    __shared__ __align__(8) uint64_t mbar[2];

    const int tid = threadIdx.x;

    // Per-thread ry (channel group == tid within every tile).
    const int c = tid * 4;
    float4 r;
    r.x = cosf(params[(c + 0) * 3]);
    r.y = cosf(params[(c + 1) * 3]);
    r.z = cosf(params[(c + 2) * 3]);
    r.w = cosf(params[(c + 3) * 3]);

    const uint32_t mb0 = smem_u32(&mbar[0]);
    const uint32_t mb1 = smem_u32(&mbar[1]);
    const uint32_t sb0 = smem_u32(s_buf[0]);
    const uint32_t sb1 = smem_u32(s_buf[1]);

    const float* gsrc = x   + (size_t)blockIdx.x * 2 * (TILE_BYTES / 4);
    float*       gdst = out + (size_t)blockIdx.x * 2 * (TILE_BYTES / 4);

    if (tid == 0) {
        asm volatile("mbarrier.init.shared.b64 [%0], 1;" :: "r"(mb0) : "memory");
        asm volatile("mbarrier.init.shared.b64 [%0], 1;" :: "r"(mb1) : "memory");
    }
    __syncthreads();

    if (tid == 0) {
        // Issue BOTH bulk loads immediately.
        asm volatile("mbarrier.arrive.expect_tx.shared.b64 _, [%0], %1;"
                     :: "r"(mb0), "r"((uint32_t)TILE_BYTES) : "memory");
        asm volatile(
            "cp.async.bulk.shared::cta.global.mbarrier::complete_tx::bytes "
            "[%0], [%1], %2, [%3];"
            :: "r"(sb0), "l"(gsrc), "r"((uint32_t)TILE_BYTES), "r"(mb0)
            : "memory");
        asm volatile("mbarrier.arrive.expect_tx.shared.b64 _, [%0], %1;"
                     :: "r"(mb1), "r"((uint32_t)TILE_BYTES) : "memory");
        asm volatile(
            "cp.async.bulk.shared::cta.global.mbarrier::complete_tx::bytes "
            "[%0], [%1], %2, [%3];"
            :: "r"(sb1), "l"(gsrc + TILE_BYTES / 4), "r"((uint32_t)TILE_BYTES), "r"(mb1)
            : "memory");
    }

    // ---- Tile 0 ----
    mbar_wait0(mb0);
#pragma unroll
    for (int i = 0; i < PER_THREAD; i++) {
        float4 v = s_buf[0][tid + i * THREADS];
        float4 o;
        o.x = __cosf(v.x) * r.x;
        o.y = __cosf(v.y) * r.y;
        o.z = __cosf(v.z) * r.z;
        o.w = __cosf(v.w) * r.w;
        s_buf[0][tid + i * THREADS] = o;   // in-place
    }
    __syncthreads();
    if (tid == 0) {
        asm volatile("fence.proxy.async.shared::cta;" ::: "memory");
        asm volatile(
            "cp.async.bulk.global.shared::cta.bulk_group [%0], [%1], %2;"
            :: "l"(gdst), "r"(sb0), "r"((uint32_t)TILE_BYTES) : "memory");
        asm volatile("cp.async.bulk.commit_group;" ::: "memory");
    }

    // ---- Tile 1 ----
    mbar_wait0(mb1);
#pragma unroll
    for (int i = 0; i < PER_THREAD; i++) {
        float4 v = s_buf[1][tid + i * THREADS];
        float4 o;
        o.x = __cosf(v.x) * r.x;
        o.y = __cosf(v.y) * r.y;
        o.z = __cosf(v.z) * r.z;
        o.w = __cosf(v.w) * r.w;
        s_buf[1][tid + i * THREADS] = o;   // in-place
    }
    __syncthreads();
    if (tid == 0) {
        asm volatile("fence.proxy.async.shared::cta;" ::: "memory");
        asm volatile(
            "cp.async.bulk.global.shared::cta.bulk_group [%0], [%1], %2;"
            :: "l"(gdst + TILE_BYTES / 4), "r"(sb1), "r"((uint32_t)TILE_BYTES)
            : "memory");
        asm volatile("cp.async.bulk.commit_group;" ::: "memory");
        asm volatile("cp.async.bulk.wait_group.read 0;" ::: "memory");
    }
}

// Fallback for any tail elements (not expected for this shape).
__global__ void qa_tail_kernel(const float* __restrict__ x,
                               const float* __restrict__ params,
                               float* __restrict__ out,
                               int start, int n)
{
    int i = start + blockIdx.x * blockDim.x + threadIdx.x;
    if (i < n) {
        float ry = cosf(params[(i & 1023) * 3]);
        out[i] = __cosf(x[i]) * ry;
    }
}

extern "C" void kernel_launch(void* const* d_in, const int* in_sizes, int n_in,
                              void* d_out, int out_size)
{
    const float* x      = (const float*)d_in[0];
    const float* params = (const float*)d_in[1];
    float* out          = (float*)d_out;

    int n = in_sizes[0];                       // 67,108,864
    int floats_per_cta = 2 * TILE_BYTES / 4;   // 8192
    int nctas = n / floats_per_cta;            // 8192
    int covered = nctas * floats_per_cta;

    if (nctas > 0)
        qa_bulk2_kernel<<<nctas, THREADS>>>(x, params, out);

    int tail = n - covered;
    if (tail > 0) {
        int tb = 256;
        qa_tail_kernel<<<(tail + tb - 1) / tb, tb>>>(x, params, out, covered, n);
    }
}